// round 11
// baseline (speedup 1.0000x reference)
#include <cuda_runtime.h>

// Problem: volume [40,40,40,32] f32, M [32,32], P [32,32] -> Nk [59319,32]
//   b = (k1*39 + k2)*39 + k3
//   Nk[b,i] = sum_j x[b,j] * P[i,j] * cos(k1*a_ij) * cos(k2*a_ij) * cos(k3*a_ij)
//   a_ij = 2pi/(i*32+j+2),  x = (2x2x2 mean pool) @ M^T
//
// R11: block = one (k1,k2) pair, 128 threads. Warp w owns k3 chunk [10w, 10w+10).
// Outer loop jp (16 f32x2 j-pairs), inner Chebyshev march over the chunk,
// acc[10] f32x2 accumulators over k3 (20 regs instead of 128 regs of j-state).
//   w_k = s_k u_k (s = +,+,-,- period 4):  even k: w = -2c*w' + w'' ; odd: +2c
// Chunk seeds from g_tab rows c0, c0+1 (both have sign s(c0) since c0 even)
// -> uniform 'flip' applied at the output store. s_k3 folded into x rows.
#define NP    39
#define NPAIR (39*39)     // 1521
#define PI2F  6.2831853071795864769f

typedef unsigned long long ull;

// g_tab relaid for j-pair-packed 8B loads:
//   g_tab[k*1024 + (j>>1)*64 + i*2 + (j&1)] = cos(k * 2pi/(i*32+j+2))
__device__ __align__(16) float g_tab[39 * 1024];

// ---- f32x2 packed math (sm_103a) ------------------------------------------
__device__ __forceinline__ ull f2_mul(ull a, ull b) {
    ull d; asm("mul.rn.f32x2 %0, %1, %2;" : "=l"(d) : "l"(a), "l"(b)); return d;
}
__device__ __forceinline__ ull f2_fma(ull a, ull b, ull c) {
    ull d; asm("fma.rn.f32x2 %0, %1, %2, %3;" : "=l"(d) : "l"(a), "l"(b), "l"(c)); return d;
}
__device__ __forceinline__ float2 f2_unpack(ull v) {
    float2 r; asm("mov.b64 {%0, %1}, %2;" : "=f"(r.x), "=f"(r.y) : "l"(v)); return r;
}

// ---------------------------------------------------------------------------
// Kernel 0: cos table (Chebyshev over k), relaid layout. grid 4 x 256.
// ---------------------------------------------------------------------------
__global__ void k_pre() {
    int t = blockIdx.x * 256 + threadIdx.x;   // t = j*32 + i
    int i = t & 31, j = t >> 5;
    int addr = (j >> 1) * 64 + i * 2 + (j & 1);
    float a  = PI2F / (float)(i * 32 + j + 2);
    float c1 = cosf(a);
    float twoc = 2.0f * c1;
    float cm2 = 1.0f, cm1 = c1;
    g_tab[addr]        = 1.0f;
    g_tab[1024 + addr] = c1;
#pragma unroll
    for (int k = 2; k < 39; k++) {
        float ck = twoc * cm1 - cm2;
        g_tab[k * 1024 + addr] = ck;
        cm2 = cm1; cm1 = ck;
    }
}

// ---------------------------------------------------------------------------
// Main kernel: grid 1521 x 128 threads, 27.1 KB static smem.
// ---------------------------------------------------------------------------
// smem float offsets (all 8B-aligned):
#define S_MT    0        // 1024  MT[l*32 + j] = M[j][l]
#define S_A     1024     // 1024  A[jp*64 + i*2 + par] = P*c1*c2
#define S_P2    2048     // 1024  +2c  (same layout)
#define S_M2    3072     // 1024  -2c
#define S_X     4096     // 1280  x'[k3*32 + j] (sign folded; row 39 = pad)
#define S_POOL  5376     // 1404  pooled[k3*36 + ch]
#define SM_FLOATS 6780

__global__ void __launch_bounds__(128) k_main(
    const float* __restrict__ vol, const float* __restrict__ Mw,
    const float* __restrict__ P, float* __restrict__ out)
{
    __shared__ float sm[SM_FLOATS];
    const int tid  = threadIdx.x;
    const int lane = tid & 31;
    const int wid  = tid >> 5;
    const int pair = blockIdx.x;
    const int k1 = pair / 39, k2 = pair - k1 * 39;

    // -------- Phase 1: MT transpose, A/P2/M2 staging, pooling --------
    for (int t = tid; t < 1024; t += 128)
        sm[S_MT + t] = Mw[(t & 31) * 32 + (t >> 5)];          // MT[l][j] = M[j][l]

    for (int g = tid; g < 1024; g += 128) {
        int i = g & 31, j = g >> 5;
        int addr = (j >> 1) * 64 + i * 2 + (j & 1);
        float tc = g_tab[1024 + addr];                         // cos(a_ij)
        sm[S_A  + addr] = P[i * 32 + j]
                        * g_tab[k1 * 1024 + addr] * g_tab[k2 * 1024 + addr];
        sm[S_P2 + addr] =  2.0f * tc;
        sm[S_M2 + addr] = -2.0f * tc;
    }

    for (int job = tid; job < 312; job += 128) {               // (k3, ch-quad)
        int k3 = job >> 3, cq = job & 7;
        const float* base = vol + (((k1 * 40) + k2) * 40 + k3) * 32 + cq * 4;
        float4 s = make_float4(0.f, 0.f, 0.f, 0.f);
#pragma unroll
        for (int dd = 0; dd < 2; dd++)
#pragma unroll
            for (int hh = 0; hh < 2; hh++)
#pragma unroll
                for (int ww = 0; ww < 2; ww++) {
                    float4 v = *(const float4*)(base + dd * 51200 + hh * 1280 + ww * 32);
                    s.x += v.x; s.y += v.y; s.z += v.z; s.w += v.w;
                }
        s.x *= 0.125f; s.y *= 0.125f; s.z *= 0.125f; s.w *= 0.125f;
        *(float4*)&sm[S_POOL + k3 * 36 + cq * 4] = s;
    }
    __syncthreads();

    // -------- Phase 2: matvec x'[k3][j] = s_k3 * (pooled[k3] @ M^T) --------
    for (int job = tid; job < 312; job += 128) {               // (k3, j-quad)
        int k3 = job >> 3, jq = job & 7;
        float a0 = 0.f, a1 = 0.f, a2 = 0.f, a3 = 0.f;
#pragma unroll
        for (int l = 0; l < 32; l++) {
            float p4 = sm[S_POOL + k3 * 36 + l];
            float4 m4 = *(const float4*)&sm[S_MT + l * 32 + jq * 4];
            a0 += p4 * m4.x; a1 += p4 * m4.y; a2 += p4 * m4.z; a3 += p4 * m4.w;
        }
        float sgn = (k3 & 2) ? -1.0f : 1.0f;                   // s_k: +,+,-,-
        float* xd = &sm[S_X + k3 * 32 + jq * 4];
        xd[0] = sgn * a0; xd[1] = sgn * a1; xd[2] = sgn * a2; xd[3] = sgn * a3;
    }
    __syncthreads();

    // -------- Phase 3: per-warp k3 chunk, Chebyshev march over t --------
    const int c0 = wid * 10;                                    // 0,10,20,30
    const int len = (c0 + 10 <= NP) ? 10 : (NP - c0);           // 10,10,10,9
    const float flip = (c0 & 2) ? -1.0f : 1.0f;                 // s(c0)=s(c0+1)

    const ull* Au  = (const ull*)(sm + S_A);
    const ull* P2u = (const ull*)(sm + S_P2);
    const ull* M2u = (const ull*)(sm + S_M2);
    const ull* Xu  = (const ull*)(sm + S_X);
    const ull* T0  = (const ull*)(g_tab + c0 * 1024);
    const ull* T1  = (const ull*)(g_tab + (c0 + 1) * 1024);

    ull acc[10];
#pragma unroll
    for (int t = 0; t < 10; t++) acc[t] = 0ull;

#pragma unroll 2
    for (int jp = 0; jp < 16; jp++) {
        int idx = jp * 32 + lane;
        ull t0 = __ldg(T0 + idx);
        ull t1 = __ldg(T1 + idx);
        ull A  = Au[idx];
        ull p2 = P2u[idx];
        ull m2 = M2u[idx];
        ull w0 = f2_mul(A, t0);                                 // w~_{c0}
        ull w1 = f2_mul(A, t1);                                 // w~_{c0+1}
        acc[0] = f2_fma(w0, Xu[(c0 + 0) * 16 + jp], acc[0]);
        acc[1] = f2_fma(w1, Xu[(c0 + 1) * 16 + jp], acc[1]);
#pragma unroll
        for (int t = 2; t < 10; t++) {
            // k = c0+t; parity(k) = parity(t) since c0 even.
            ull w = (t & 1) ? f2_fma(p2, w1, w0)                // odd:  +2c*w' + w''
                            : f2_fma(m2, w1, w0);               // even: -2c*w' + w''
            w0 = w1; w1 = w;
            if (c0 + t < NP)
                acc[t] = f2_fma(w, Xu[(c0 + t) * 16 + jp], acc[t]);
        }
    }

#pragma unroll
    for (int t = 0; t < 10; t++) {
        if (t < len) {
            float2 f = f2_unpack(acc[t]);
            out[(pair * NP + c0 + t) * 32 + lane] = flip * (f.x + f.y);
        }
    }
}

// ---------------------------------------------------------------------------
extern "C" void kernel_launch(void* const* d_in, const int* in_sizes, int n_in,
                              void* d_out, int out_size) {
    const float* vol = (const float*)d_in[0];
    const float* M   = (const float*)d_in[1];
    const float* P   = (const float*)d_in[2];
    float* out = (float*)d_out;

    k_pre <<<4, 256>>>();
    k_main<<<NPAIR, 128>>>(vol, M, P, out);
}

// round 12
// speedup vs baseline: 1.3763x; 1.3763x over previous
#include <cuda_runtime.h>

// Problem: volume [40,40,40,32] f32, M [32,32], P [32,32] -> Nk [59319,32]
//   b = (k1*39 + k2)*39 + k3
//   Nk[b,i] = sum_j x[b,j] * P[i,j] * cos(k1*a_ij) * cos(k2*a_ij) * cos(k3*a_ij)
//   a_ij = 2pi/(i*32+j+2),  x = (2x2x2 mean pool) @ M^T
//
// R12: register-resident Chebyshev march over k3 (as R9), but j is split
// across TWO warps per (k1,k2) pair -> per-warp state halves (64 regs),
// ~105 total regs -> 3 blocks/SM (18 warps) instead of R9's 11 warps.
//   w_k = s_k u_k (s = +,+,-,- period 4): even k: w = -2c*w1 + w0; odd: +2c
// Sign s_k folded into staged x rows. Each warp stores a scalar partial per
// k3; a combine pass adds the two halves and writes out.
#define NP    39
#define NPAIR (39*39)     // 1521 = 507 * 3
#define PPB   3           // pairs per block
#define TPB   (PPB*2*32)  // 192 threads = 6 warps
#define PI2F  6.2831853071795864769f

typedef unsigned long long ull;

__device__ float g_tab[39 * 1024];   // tab[k][j*32+i] = cos(k*2pi/(i*32+j+2))

// ---- f32x2 packed math (sm_103a) ------------------------------------------
__device__ __forceinline__ ull f2_fma(ull a, ull b, ull c) {
    ull d; asm("fma.rn.f32x2 %0, %1, %2, %3;" : "=l"(d) : "l"(a), "l"(b), "l"(c)); return d;
}
__device__ __forceinline__ ull f2_add(ull a, ull b) {
    ull d; asm("add.rn.f32x2 %0, %1, %2;" : "=l"(d) : "l"(a), "l"(b)); return d;
}
__device__ __forceinline__ ull f2_pack2(float lo, float hi) {
    ull d; asm("mov.b64 %0, {%1, %2};" : "=l"(d) : "f"(lo), "f"(hi)); return d;
}
__device__ __forceinline__ float2 f2_unpack(ull v) {
    float2 r; asm("mov.b64 {%0, %1}, %2;" : "=f"(r.x), "=f"(r.y) : "l"(v)); return r;
}

// ---------------------------------------------------------------------------
// Kernel 0: cos table via Chebyshev recurrence. grid 4 x 256.
// ---------------------------------------------------------------------------
__global__ void k_pre() {
    int t = blockIdx.x * 256 + threadIdx.x;   // t = j*32 + i
    int i = t & 31, j = t >> 5;
    float a  = PI2F / (float)(i * 32 + j + 2);
    float c1 = cosf(a);
    float twoc = 2.0f * c1;
    float cm2 = 1.0f, cm1 = c1;
    g_tab[t]        = 1.0f;
    g_tab[1024 + t] = c1;
#pragma unroll
    for (int k = 2; k < 39; k++) {
        float ck = twoc * cm1 - cm2;
        g_tab[k * 1024 + t] = ck;
        cm2 = cm1; cm1 = ck;
    }
}

// ---------------------------------------------------------------------------
// Main kernel: grid 507 x 192 threads, 43.9 KB static smem.
// Warp layout: warp w -> pair lp = w>>1 (0..2), half jh = w&1.
// ---------------------------------------------------------------------------
// smem float offsets:
//   setup region (dead before march) overlapped by PART:
#define S_MS    0        // 1056   M padded  [j*33 + l]
#define S_PT    1056     // 1056   P^T padded [j*33 + i]   (read by seeds)
#define S_MT    2112     // 1024   MT[l*32 + j]
#define S_POOL  3136     // 3*1404 = 4212  pooled[lp][k3*36 + ch]
#define S_PART  0        // 3*2*39*32 = 7488  partial[lp][jh][k3*32 + lane]
#define S_X     7488     // 3*1248 = 3744     x'[lp][k3*32 + j] (sign folded)
#define SM_FLOATS 11232

__global__ void __launch_bounds__(TPB) k_main(
    const float* __restrict__ vol, const float* __restrict__ Mw,
    const float* __restrict__ P, float* __restrict__ out)
{
    __shared__ float sm[SM_FLOATS];
    const int tid  = threadIdx.x;
    const int lane = tid & 31;
    const int wid  = tid >> 5;
    const int lp   = wid >> 1;                 // pair within block (0..2)
    const int jh   = wid & 1;                  // j half (0: j<16, 1: j>=16)
    const int pair = blockIdx.x * PPB + lp;
    const int k1 = pair / 39, k2 = pair - (pair / 39) * 39;

    // -------- Phase A: stage padded M and transposed-padded P --------
    for (int g = tid; g < 1024; g += TPB) {
        sm[S_MS + (g >> 5) * 33 + (g & 31)] = Mw[g];          // MS[j][l]
        sm[S_PT + (g & 31) * 33 + (g >> 5)] = P[g];           // PT[j][i] = P[i][j]
    }
    __syncthreads();

    // -------- Phase B: MT transpose + pooling (3 pairs) --------
    for (int t = tid; t < 1024; t += TPB)
        sm[S_MT + t] = sm[S_MS + (t & 31) * 33 + (t >> 5)];   // MT[l][j] = M[j][l]

    for (int job = tid; job < PPB * 312; job += TPB) {
        int p   = job / 312;
        int rem = job - p * 312;
        int k3  = rem >> 3;
        int cq  = rem & 7;
        int gp  = blockIdx.x * PPB + p;
        int kk1 = gp / 39, kk2 = gp - kk1 * 39;
        const float* base = vol + (((kk1 * 40) + kk2) * 40 + k3) * 32 + cq * 4;
        float4 s = make_float4(0.f, 0.f, 0.f, 0.f);
#pragma unroll
        for (int dd = 0; dd < 2; dd++)
#pragma unroll
            for (int hh = 0; hh < 2; hh++)
#pragma unroll
                for (int ww = 0; ww < 2; ww++) {
                    float4 v = *(const float4*)(base + dd * 51200 + hh * 1280 + ww * 32);
                    s.x += v.x; s.y += v.y; s.z += v.z; s.w += v.w;
                }
        s.x *= 0.125f; s.y *= 0.125f; s.z *= 0.125f; s.w *= 0.125f;
        *(float4*)&sm[S_POOL + p * 1404 + k3 * 36 + cq * 4] = s;
    }
    __syncthreads();

    // -------- Phase C: matvec x'[lp][k3][j] = s_k3 * (pooled @ M^T) --------
    for (int job = tid; job < PPB * 312; job += TPB) {
        int p   = job / 312;
        int rem = job - p * 312;
        int k3  = rem >> 3;
        int jq  = rem & 7;
        float a0 = 0.f, a1 = 0.f, a2 = 0.f, a3 = 0.f;
#pragma unroll
        for (int l = 0; l < 32; l++) {
            float p4 = sm[S_POOL + p * 1404 + k3 * 36 + l];
            float4 m4 = *(const float4*)&sm[S_MT + l * 32 + jq * 4];
            a0 += p4 * m4.x; a1 += p4 * m4.y; a2 += p4 * m4.z; a3 += p4 * m4.w;
        }
        float sgn = (k3 & 2) ? -1.0f : 1.0f;                 // s_k: +,+,-,-
        float* xd = &sm[S_X + p * 1248 + k3 * 32 + jq * 4];
        xd[0] = sgn * a0; xd[1] = sgn * a1; xd[2] = sgn * a2; xd[3] = sgn * a3;
    }
    __syncthreads();

    // -------- Phase D: per-warp seeds (reads PT smem + g_tab) --------
    const float* t1r = g_tab + k1 * 1024;
    const float* t2r = g_tab + k2 * 1024;
    const float* cr  = g_tab + 1024;                          // k=1 row: cos(a)

    ull w0[8], w1[8], p2[8], m2[8];
#pragma unroll
    for (int jp = 0; jp < 8; jp++) {
        int jpg = jh * 8 + jp;                                // global j-pair
        int t0 = (2 * jpg) * 32 + lane, t1 = t0 + 32;
        float pa = sm[S_PT + (2 * jpg) * 33 + lane];
        float pb = sm[S_PT + (2 * jpg + 1) * 33 + lane];
        float a0 = pa * t1r[t0] * t2r[t0];                    // A[i, 2jpg]
        float a1 = pb * t1r[t1] * t2r[t1];                    // A[i, 2jpg+1]
        float c0 = cr[t0], c1 = cr[t1];
        w0[jp] = f2_pack2(a0, a1);                            // w_0 = A
        w1[jp] = f2_pack2(a0 * c0, a1 * c1);                  // w_1 = A*c
        p2[jp] = f2_pack2(2.0f * c0, 2.0f * c1);              // +2c
        m2[jp] = f2_pack2(-2.0f * c0, -2.0f * c1);            // -2c
    }
    __syncthreads();   // PT (inside PART region) fully consumed before STS

    // -------- Phase E: march k3; per-warp half-dot partial -> smem --------
    const ulonglong2* xq = (const ulonglong2*)(sm + S_X + lp * 1248) + jh * 4;
    float* partw = sm + S_PART + (lp * 2 + jh) * 1248 + lane;
    ulonglong2 xb[4];

#define XLOAD(K3) do { _Pragma("unroll")                                  \
    for (int q = 0; q < 4; q++) xb[q] = xq[(K3) * 8 + q]; } while (0)

#define DOT_PART(W, K3) do {                                              \
    ull a0 = 0, a1 = 0, a2 = 0, a3 = 0;                                   \
    a0 = f2_fma(W[0], xb[0].x, a0);  a1 = f2_fma(W[1], xb[0].y, a1);      \
    a2 = f2_fma(W[2], xb[1].x, a2);  a3 = f2_fma(W[3], xb[1].y, a3);      \
    a0 = f2_fma(W[4], xb[2].x, a0);  a1 = f2_fma(W[5], xb[2].y, a1);      \
    a2 = f2_fma(W[6], xb[3].x, a2);  a3 = f2_fma(W[7], xb[3].y, a3);      \
    float2 fr = f2_unpack(f2_add(f2_add(a0, a1), f2_add(a2, a3)));        \
    partw[(K3) * 32] = fr.x + fr.y;                                       \
} while (0)

    XLOAD(0); DOT_PART(w0, 0);
    XLOAD(1); DOT_PART(w1, 1);

#pragma unroll 1
    for (int k3 = 2; k3 < 38; k3 += 2) {
        XLOAD(k3);                                            // LDS hoisted
#pragma unroll
        for (int jp = 0; jp < 8; jp++)
            w0[jp] = f2_fma(m2[jp], w1[jp], w0[jp]);          // even: -2c*w1 + w0
        DOT_PART(w0, k3);
        XLOAD(k3 + 1);
#pragma unroll
        for (int jp = 0; jp < 8; jp++)
            w1[jp] = f2_fma(p2[jp], w0[jp], w1[jp]);          // odd: +2c*w0 + w1
        DOT_PART(w1, k3 + 1);
    }
    XLOAD(38);
#pragma unroll
    for (int jp = 0; jp < 8; jp++)
        w0[jp] = f2_fma(m2[jp], w1[jp], w0[jp]);
    DOT_PART(w0, 38);
#undef XLOAD
#undef DOT_PART

    __syncthreads();

    // -------- Phase F: combine halves, store --------
    for (int idx = tid; idx < PPB * 1248; idx += TPB) {
        int p = idx / 1248;
        int r = idx - p * 1248;                               // k3*32 + i
        float v = sm[S_PART + p * 2496 + r] + sm[S_PART + p * 2496 + 1248 + r];
        out[(blockIdx.x * PPB + p) * 1248 + r] = v;
    }
}

// ---------------------------------------------------------------------------
extern "C" void kernel_launch(void* const* d_in, const int* in_sizes, int n_in,
                              void* d_out, int out_size) {
    const float* vol = (const float*)d_in[0];
    const float* M   = (const float*)d_in[1];
    const float* P   = (const float*)d_in[2];
    float* out = (float*)d_out;

    k_pre <<<4, 256>>>();
    k_main<<<NPAIR / PPB, TPB>>>(vol, M, P, out);   // 507 blocks
}